// round 9
// baseline (speedup 1.0000x reference)
#include <cuda_runtime.h>
#include <math.h>

// DBN beat decoder (bar-pointer Viterbi). B=4, T=6000, 82 blocks, S=5617.
//
// R7: issue-bandwidth redesign. Shared-memory delta (ping-pong), ONE barrier
// per step. Bulk update is branch-free: per-slot precomputed load index points
// at cur[s-1] (normal), vf[j] (position-1 slots), or a safe cell (s==0).
// First states store junk (never read; final argmax substitutes vf).
// pl_t[i] = cur[last_i-1] + nb_t computed pre-bulk (last-1 never first).
// vf_t[j] = fb_t[j] + b_t written directly by the reduction leader.
// Backpointers compressed to 82 prev_last floats/step (g_plbuf); argmax
// recomputed at ~90 beat jumps in backtracking (first-index tiebreak).

#define NI      82
#define MINTAU  28
#define NSTATE  5617
#define TT      6000
#define BB      4
#define NTHREADS 768
#define NSLOTS  8      // 768*8 = 6144 >= 5617 (pads harmless)

// shared-memory layout (float offsets)
#define OFF_B0   0          // delta buffer, even t   (6144)
#define OFF_B1   6144       // delta buffer, odd t    (6144)
#define OFF_TL   12288      // trans_log 82x82        (6724)
#define OFF_BLP  19012      // beat logprob           (6000)
#define OFF_NB   25012      // nonbeat logprob        (6000)
#define OFF_PL0  31012      // prev_last, even parity (96, pad -inf, 16B aligned)
#define OFF_PL1  31108      // prev_last, odd parity  (96)
#define OFF_VF0  31204      // virtual first, even    (96)
#define OFF_VF1  31300      // virtual first, odd     (96)
#define OFF_RV   31396      // argmax values          (768+)
#define OFF_RI   32420      // argmax indices         (768+)
#define SM_FLOATS 33444

__device__ float g_plbuf[BB][TT + 1][NI];

__device__ __forceinline__ int base_of(int j) {
    return MINTAU * j + (j * (j - 1)) / 2;
}

__global__ void __launch_bounds__(NTHREADS, 1)
dbn_viterbi_kernel(const float* __restrict__ logit, float* __restrict__ out)
{
    extern __shared__ float sm[];
    const int tid  = threadIdx.x;
    const int wrp  = tid >> 5;
    const int b    = blockIdx.x;
    const float* lg = logit + b * TT;
    float* outrow   = out + b * TT;

    const float NEGINF = __int_as_float(0xff800000);

    // ---- zero output row ----
    for (int t = tid; t < TT; t += NTHREADS) outrow[t] = 0.0f;

    // ---- emissions (double precision, cast to f32; bit-matched reference) ----
    for (int t = tid; t < TT; t += NTHREADS) {
        double x = (double)lg[t];
        double bl = (x >= 0.0) ? -log1p(exp(-x)) : (x - log1p(exp(x)));
        double nl = (x <= 0.0) ? -log1p(exp(x))  : (-x - log1p(exp(-x)));
        sm[OFF_BLP + t] = (float)bl;
        sm[OFF_NB  + t] = (float)nl;
    }

    // ---- trans_log rows (double precision log-softmax) ----
    if (tid < NI) {
        int i = tid;
        double ti = (double)(MINTAU + i);
        double ssum = 0.0;
        for (int j = 0; j < NI; ++j) {
            double r = -100.0 * fabs((double)(MINTAU + j) / ti - 1.0);
            ssum += exp(r);
        }
        double ls = log(ssum);  // row max is 0 (at j==i)
        for (int j = 0; j < NI; ++j) {
            double r = -100.0 * fabs((double)(MINTAU + j) / ti - 1.0);
            sm[OFF_TL + i * NI + j] = (float)(r - ls);
        }
    }
    if (tid < 14) {  // -inf pads for reduction overshoot, both parities
        sm[OFF_PL0 + 82 + tid] = NEGINF;
        sm[OFF_PL1 + 82 + tid] = NEGINF;
    }

    // ---- per-slot metadata: branch-free load indices + masks ----
    int lidxO[NSLOTS], lidxE[NSLOTS];
    unsigned firstM = 0, validM = 0;
    #pragma unroll
    for (int k = 0; k < NSLOTS; ++k) {
        int s = tid + k * NTHREADS;
        if (s < NSTATE) {
            validM |= 1u << k;
            int j = 0;
            while (j < NI - 1 && base_of(j + 1) <= s) ++j;
            int pos = s - base_of(j);
            if (pos == 0) firstM |= 1u << k;
            if (pos == 1)      { lidxO[k] = OFF_VF0 + j;     lidxE[k] = OFF_VF1 + j; }
            else if (s == 0)   { lidxO[k] = OFF_B0;          lidxE[k] = OFF_B1; }          // safe junk
            else               { lidxO[k] = OFF_B0 + s - 1;  lidxE[k] = OFF_B1 + s - 1; }
        } else {
            lidxO[k] = OFF_B0 + s - 1;  lidxE[k] = OFF_B1 + s - 1;   // pad, harmless
        }
    }

    // pl-extract role: tids 672..753 (warps 21-23, no shuffles there)
    const bool plThread = (tid >= 672) && (tid < 672 + NI);
    const int  plIdx    = tid - 672;
    const int  lastm1   = plThread ? (base_of(plIdx + 1) - 2) : 0;

    const float logS = (float)log((double)NSTATE);

    __syncthreads();  // emissions + trans_log ready

    // ---- preload trans_log candidates (8 lanes per j; groups padded to 84) ----
    const int rj = tid >> 3, rg = tid & 7;
    float tlr[12];
    #pragma unroll
    for (int q = 0; q < 12; ++q) {
        int i = 4 * rg + 32 * (q >> 2) + (q & 3);
        tlr[q] = (rj < NI && i < NI) ? sm[OFF_TL + i * NI + rj] : 0.0f;  // pl pad = -inf
    }

    // ---- init delta(0) into buf0 ----
    {
        float bt0 = sm[OFF_BLP + 0], nbt0 = sm[OFF_NB + 0];
        #pragma unroll
        for (int k = 0; k < NSLOTS; ++k) {
            int s = tid + k * NTHREADS;
            float em = ((firstM >> k) & 1u) ? bt0 : nbt0;
            sm[OFF_B0 + s] = em - logS;   // pads get a finite value, harmless
        }
    }
    __syncthreads();
    if (tid < NI) {  // pl0, vf0, plbuf row 1
        int i = tid;
        float plv = sm[OFF_B0 + base_of(i + 1) - 1];
        sm[OFF_PL0 + i] = plv;
        g_plbuf[b][1][i] = plv;
        sm[OFF_VF0 + i] = sm[OFF_B0 + base_of(i)];
    }

    // ---- forward Viterbi: one barrier per step, unrolled x2 by parity ----
#define STEP(T, CUR, ST, PLPREV, PLCUR, VFCUR, LIDX) do {                         \
        __syncthreads();                                                          \
        const float nbt = sm[OFF_NB + (T)];                                       \
        if (wrp < 21) {                                                           \
            const float4 p0 = *(const float4*)&sm[(PLPREV) + 4 * rg];             \
            const float4 p1 = *(const float4*)&sm[(PLPREV) + 32 + 4 * rg];        \
            const float4 p2 = *(const float4*)&sm[(PLPREV) + 64 + 4 * rg];        \
            float a0 = p0.x + tlr[0],  a1 = p0.y + tlr[1];                        \
            a0 = fmaxf(a0, p0.z + tlr[2]);  a1 = fmaxf(a1, p0.w + tlr[3]);        \
            a0 = fmaxf(a0, p1.x + tlr[4]);  a1 = fmaxf(a1, p1.y + tlr[5]);        \
            a0 = fmaxf(a0, p1.z + tlr[6]);  a1 = fmaxf(a1, p1.w + tlr[7]);        \
            a0 = fmaxf(a0, p2.x + tlr[8]);  a1 = fmaxf(a1, p2.y + tlr[9]);        \
            a0 = fmaxf(a0, p2.z + tlr[10]); a1 = fmaxf(a1, p2.w + tlr[11]);       \
            float best = fmaxf(a0, a1);                                           \
            best = fmaxf(best, __shfl_xor_sync(0xffffffffu, best, 1));            \
            best = fmaxf(best, __shfl_xor_sync(0xffffffffu, best, 2));            \
            best = fmaxf(best, __shfl_xor_sync(0xffffffffu, best, 4));            \
            if (rg == 0 && rj < NI)                                               \
                sm[(VFCUR) + rj] = best + sm[OFF_BLP + (T)];                      \
        } else if (plThread) {                                                    \
            float plv = sm[(CUR) + lastm1] + nbt;                                 \
            sm[(PLCUR) + plIdx] = plv;                                            \
            g_plbuf[b][(T) + 1][plIdx] = plv;                                     \
        }                                                                         \
        float x0 = sm[LIDX[0]] + nbt;  float x1 = sm[LIDX[1]] + nbt;              \
        float x2 = sm[LIDX[2]] + nbt;  float x3 = sm[LIDX[3]] + nbt;              \
        float x4 = sm[LIDX[4]] + nbt;  float x5 = sm[LIDX[5]] + nbt;              \
        float x6 = sm[LIDX[6]] + nbt;  float x7 = sm[LIDX[7]] + nbt;              \
        sm[(ST) + tid             ] = x0;  sm[(ST) + tid + 1 * NTHREADS] = x1;    \
        sm[(ST) + tid + 2*NTHREADS] = x2;  sm[(ST) + tid + 3 * NTHREADS] = x3;    \
        sm[(ST) + tid + 4*NTHREADS] = x4;  sm[(ST) + tid + 5 * NTHREADS] = x5;    \
        sm[(ST) + tid + 6*NTHREADS] = x6;  sm[(ST) + tid + 7 * NTHREADS] = x7;    \
    } while (0)

    for (int t = 1; t < TT - 1; t += 2) {
        STEP(t,     OFF_B0, OFF_B1, OFF_PL0, OFF_PL1, OFF_VF1, lidxO);
        STEP(t + 1, OFF_B1, OFF_B0, OFF_PL1, OFF_PL0, OFF_VF0, lidxE);
    }
    STEP(TT - 1, OFF_B0, OFF_B1, OFF_PL0, OFF_PL1, OFF_VF1, lidxO);
    // final delta in buf1 (non-first states); first states in vf1.

    // ---- final argmax over delta(T-1), first-index tiebreak ----
    __syncthreads();
    {
        float bv = NEGINF; int bs = NSTATE - 1;
        #pragma unroll
        for (int k = 0; k < NSLOTS; ++k) {
            if ((validM >> k) & 1u) {
                int s = tid + k * NTHREADS;
                float val;
                if ((firstM >> k) & 1u) {
                    int j = 0;
                    while (j < NI - 1 && base_of(j + 1) <= s) ++j;
                    val = sm[OFF_VF1 + j];
                } else {
                    val = sm[OFF_B1 + s];
                }
                if (val > bv) { bv = val; bs = s; }
            }
        }
        sm[OFF_RV + tid] = bv;
        ((int*)sm)[OFF_RI + tid] = bs;
    }
    __syncthreads();
    if (tid < NTHREADS - 512) {   // fold 512..767 into 0..255
        float v2 = sm[OFF_RV + tid + 512]; int s2 = ((int*)sm)[OFF_RI + tid + 512];
        if (v2 > sm[OFF_RV + tid] ||
            (v2 == sm[OFF_RV + tid] && s2 < ((int*)sm)[OFF_RI + tid])) {
            sm[OFF_RV + tid] = v2; ((int*)sm)[OFF_RI + tid] = s2;
        }
    }
    __syncthreads();
    for (int st = 256; st > 0; st >>= 1) {
        if (tid < st) {
            float v2 = sm[OFF_RV + tid + st]; int s2 = ((int*)sm)[OFF_RI + tid + st];
            if (v2 > sm[OFF_RV + tid] ||
                (v2 == sm[OFF_RV + tid] && s2 < ((int*)sm)[OFF_RI + tid])) {
                sm[OFF_RV + tid] = v2; ((int*)sm)[OFF_RI + tid] = s2;
            }
        }
        __syncthreads();
    }

    // ---- backtrack (thread 0): jump beat-to-beat, hard-bounded ----
    if (tid == 0) {
        const double p0  = (double)0.05f;
        const double thr = log(p0 / (1.0 - p0));   // logit-space threshold

        int s = ((int*)sm)[OFF_RI + 0];
        if (s < 0) s = 0;
        if (s >= NSTATE) s = NSTATE - 1;
        int j = 0;
        while (j < NI - 1 && base_of(j + 1) <= s) ++j;
        int p = s - base_of(j);
        int t = TT - 1;
        for (int iter = 0; iter < TT; ++iter) {
            if (p > t) break;            // path started mid-block: no beat
            int tb = t - p;              // beat time (position 0)
            double x = (double)lg[tb];
            outrow[tb] = (x >= thr) ? 1.0f : 0.0f;
            if (tb == 0) break;
            const float* row = &g_plbuf[b][tb][0];
            float mx = NEGINF; int bi = 0;
            for (int i = 0; i < NI; ++i) {
                float c = row[i] + sm[OFF_TL + i * NI + j];
                if (c > mx) { mx = c; bi = i; }
            }
            j = bi;
            t = tb - 1;
            p = (MINTAU + j) - 1;
        }
    }
}

extern "C" void kernel_launch(void* const* d_in, const int* in_sizes, int n_in,
                              void* d_out, int out_size)
{
    const float* logit = (const float*)d_in[0];
    float* out = (float*)d_out;

    size_t smem = (size_t)SM_FLOATS * sizeof(float);   // 133,776 B
    cudaFuncSetAttribute(dbn_viterbi_kernel,
                         cudaFuncAttributeMaxDynamicSharedMemorySize, (int)smem);
    dbn_viterbi_kernel<<<BB, NTHREADS, smem>>>(logit, out);
}

// round 10
// speedup vs baseline: 1.2163x; 1.2163x over previous
#include <cuda_runtime.h>
#include <math.h>

// DBN beat decoder (bar-pointer Viterbi). B=4, T=6000, 82 blocks, S=5617.
//
// R10: two time steps fused per ping-pong block (delta(u) -> delta(u+2)):
//   pos>=2: ((buf[s-2] + nb1) + nb2)  -- one LDS+STS per 2 steps (traffic halved)
//   pos==1: vf(u+1) + nb2             (vf scratch produced one block ahead)
//   pos==0: written by reduction leader (vf(u+2)) into the delta buffer itself
//   L(u+1)[i] = buf[last_i-1] + nb1 ; L(u+2)[i] = (buf[last_i-2]+nb1)+nb2
//     (last-1, last-2 always pos>=2 => direct from delta(u))
//   Two reductions per block (fb(u+2) from L(u+1), fb(u+3) from L(u+2)),
//   shuffle chains interleaved. Branch-free pos-1 via fmaf(nb1, m, x), m in {0,1}
//   (bit-exact: nb1*1 exact; x + -0 = x, deltas strictly negative).
// Backpointers compressed to 82 prev_last floats/step (g_plbuf); argmax
// recomputed at ~90 beat jumps in backtracking (first-index tiebreak).

#define NI      82
#define MINTAU  28
#define NSTATE  5617
#define TT      6000
#define BB      4
#define NTHREADS 768
#define NSLOTS  8      // 768*8 = 6144 >= 5617

// shared-memory layout (float offsets)
#define OFF_A    0          // delta buffer A          (6144)
#define OFF_B    6144       // delta buffer B          (6144)
#define OFF_TL   12288      // trans_log 82x82         (6724)
#define OFF_BLP  19012      // beat logprob            (6000)
#define OFF_NB   25012      // nonbeat logprob         (6000)
#define OFF_LA   31012      // L(u+1), pad[82..95]=-inf (96, 16B aligned)
#define OFF_LB   31108      // L(u+2), pad[82..95]=-inf (96)
#define OFF_VF   31204      // vf scratch (odd times)   (84)
#define OFF_RV   31288      // argmax values            (768)
#define OFF_RI   32056      // argmax indices           (768)
#define SM_FLOATS 32824

__device__ float g_plbuf[BB][TT + 1][NI];

__device__ __forceinline__ int base_of(int j) {
    return MINTAU * j + (j * (j - 1)) / 2;
}

__global__ void __launch_bounds__(NTHREADS, 1)
dbn_viterbi_kernel(const float* __restrict__ logit, float* __restrict__ out)
{
    extern __shared__ float sm[];
    const int tid  = threadIdx.x;
    const int wrp  = tid >> 5;
    const int b    = blockIdx.x;
    const float* lg = logit + b * TT;
    float* outrow   = out + b * TT;

    const float NEGINF = __int_as_float(0xff800000);

    // ---- zero output row ----
    for (int t = tid; t < TT; t += NTHREADS) outrow[t] = 0.0f;

    // ---- emissions (double precision, cast to f32; bit-matched reference) ----
    for (int t = tid; t < TT; t += NTHREADS) {
        double x = (double)lg[t];
        double bl = (x >= 0.0) ? -log1p(exp(-x)) : (x - log1p(exp(x)));
        double nl = (x <= 0.0) ? -log1p(exp(x))  : (-x - log1p(exp(-x)));
        sm[OFF_BLP + t] = (float)bl;
        sm[OFF_NB  + t] = (float)nl;
    }

    // ---- trans_log rows (double precision log-softmax) ----
    if (tid < NI) {
        int i = tid;
        double ti = (double)(MINTAU + i);
        double ssum = 0.0;
        for (int j = 0; j < NI; ++j) {
            double r = -100.0 * fabs((double)(MINTAU + j) / ti - 1.0);
            ssum += exp(r);
        }
        double ls = log(ssum);  // row max is 0 (at j==i)
        for (int j = 0; j < NI; ++j) {
            double r = -100.0 * fabs((double)(MINTAU + j) / ti - 1.0);
            sm[OFF_TL + i * NI + j] = (float)(r - ls);
        }
    }
    if (tid < 14) {  // -inf pads for reduction overshoot (set once, never clobbered)
        sm[OFF_LA + 82 + tid] = NEGINF;
        sm[OFF_LB + 82 + tid] = NEGINF;
    }

    // ---- per-slot metadata: branch-free load indices + fmaf masks ----
    int lidxA[NSLOTS], lidxB[NSLOTS], lidxT[NSLOTS];
    float m1[NSLOTS], mT[NSLOTS];
    unsigned firstM = 0, validM = 0;
    #pragma unroll
    for (int k = 0; k < NSLOTS; ++k) {
        int s = tid + k * NTHREADS;
        int j = 0;
        while (j < NI - 1 && base_of(j + 1) <= s) ++j;
        int pos = s - base_of(j);          // meaningful for s < NSTATE
        bool valid = (s < NSTATE);
        if (valid) validM |= 1u << k;
        m1[k] = 1.0f;  mT[k] = 1.0f;
        if (valid && pos == 1) {
            lidxA[k] = OFF_VF + j;  lidxB[k] = OFF_VF + j;  m1[k] = 0.0f;
            lidxT[k] = OFF_B + s - 1;
        } else if (valid && pos == 0) {
            firstM |= 1u << k;
            lidxA[k] = OFF_A + s;   lidxB[k] = OFF_B + s;   // dummy (overwritten by leader)
            lidxT[k] = OFF_VF + j;  mT[k] = 0.0f;           // tail: vf(5999) verbatim
        } else {
            lidxA[k] = OFF_A + s - 2;  lidxB[k] = OFF_B + s - 2;
            lidxT[k] = OFF_B + s - 1;
        }
    }

    // pl role: tids 672..753 extract last-state values
    const bool plThread = (tid >= 672) && (tid < 672 + NI);
    const int  plIdx    = tid - 672;
    const int  lastIdx  = plThread ? (base_of(plIdx + 1) - 1) : 0;
    const int  lastm1   = lastIdx - 1;   // pos tau-2 >= 26
    const int  lastm2   = lastIdx - 2;   // pos tau-3 >= 25

    const float logS = (float)log((double)NSTATE);

    __syncthreads();  // emissions + trans_log ready

    // ---- preload trans_log candidates (8 lanes per j-group; groups padded to 84) ----
    const int rj = tid >> 3, rg = tid & 7;
    const int baseRJ = (rj < NI) ? base_of(rj) : 0;
    float tlr[12];
    #pragma unroll
    for (int q = 0; q < 12; ++q) {
        int i = 4 * rg + 32 * (q >> 2) + (q & 3);
        tlr[q] = (rj < NI && i < NI) ? sm[OFF_TL + i * NI + rj] : 0.0f;  // L pad = -inf
    }

    // ---- init delta(0) into buffer A (all cells valid incl. first states) ----
    {
        float bt0 = sm[OFF_BLP + 0], nbt0 = sm[OFF_NB + 0];
        #pragma unroll
        for (int k = 0; k < NSLOTS; ++k) {
            int s = tid + k * NTHREADS;
            float em = ((firstM >> k) & 1u) ? bt0 : nbt0;
            sm[OFF_A + s] = em - logS;   // pads finite, harmless
        }
    }
    __syncthreads();
    if (plThread) {            // L(0) + backtrack row 1
        float l0 = sm[OFF_A + lastIdx];
        sm[OFF_LA + plIdx] = l0;
        g_plbuf[b][1][plIdx] = l0;
    }
    __syncthreads();
    if (wrp < 21) {            // fb(1) -> vf(1) scratch
        const float4 a0 = *(const float4*)&sm[OFF_LA + 4 * rg];
        const float4 a1 = *(const float4*)&sm[OFF_LA + 32 + 4 * rg];
        const float4 a2 = *(const float4*)&sm[OFF_LA + 64 + 4 * rg];
        float p0 = a0.x + tlr[0], p1 = a0.y + tlr[1];
        p0 = fmaxf(p0, a0.z + tlr[2]);  p1 = fmaxf(p1, a0.w + tlr[3]);
        p0 = fmaxf(p0, a1.x + tlr[4]);  p1 = fmaxf(p1, a1.y + tlr[5]);
        p0 = fmaxf(p0, a1.z + tlr[6]);  p1 = fmaxf(p1, a1.w + tlr[7]);
        p0 = fmaxf(p0, a2.x + tlr[8]);  p1 = fmaxf(p1, a2.y + tlr[9]);
        p0 = fmaxf(p0, a2.z + tlr[10]); p1 = fmaxf(p1, a2.w + tlr[11]);
        float best = fmaxf(p0, p1);
        best = fmaxf(best, __shfl_xor_sync(0xffffffffu, best, 1));
        best = fmaxf(best, __shfl_xor_sync(0xffffffffu, best, 2));
        best = fmaxf(best, __shfl_xor_sync(0xffffffffu, best, 4));
        if (rg == 0 && rj < NI) sm[OFF_VF + rj] = best + sm[OFF_BLP + 1];
    }

    // ---- fused 2-step block: delta(U) -> delta(U+2) ----
#define BLOCK(U, PREV, NEXT, LIDX) do {                                           \
        __syncthreads();  /* barrier A */                                         \
        const float nb1 = sm[OFF_NB + (U) + 1];                                   \
        const float nb2 = sm[OFF_NB + (U) + 2];                                   \
        if (plThread) {                                                           \
            float l1 = sm[(PREV) + lastm1] + nb1;                                 \
            float l2 = (sm[(PREV) + lastm2] + nb1) + nb2;                         \
            sm[OFF_LA + plIdx] = l1;                                              \
            sm[OFF_LB + plIdx] = l2;                                              \
            g_plbuf[b][(U) + 2][plIdx] = l1;                                      \
            g_plbuf[b][(U) + 3][plIdx] = l2;                                      \
        }                                                                         \
        float x0 = sm[LIDX[0]], x1 = sm[LIDX[1]], x2 = sm[LIDX[2]], x3 = sm[LIDX[3]]; \
        float x4 = sm[LIDX[4]], x5 = sm[LIDX[5]], x6 = sm[LIDX[6]], x7 = sm[LIDX[7]]; \
        sm[(NEXT) + tid             ] = fmaf(nb1, m1[0], x0) + nb2;               \
        sm[(NEXT) + tid + 1*NTHREADS] = fmaf(nb1, m1[1], x1) + nb2;               \
        sm[(NEXT) + tid + 2*NTHREADS] = fmaf(nb1, m1[2], x2) + nb2;               \
        sm[(NEXT) + tid + 3*NTHREADS] = fmaf(nb1, m1[3], x3) + nb2;               \
        sm[(NEXT) + tid + 4*NTHREADS] = fmaf(nb1, m1[4], x4) + nb2;               \
        sm[(NEXT) + tid + 5*NTHREADS] = fmaf(nb1, m1[5], x5) + nb2;               \
        sm[(NEXT) + tid + 6*NTHREADS] = fmaf(nb1, m1[6], x6) + nb2;               \
        sm[(NEXT) + tid + 7*NTHREADS] = fmaf(nb1, m1[7], x7) + nb2;               \
        __syncthreads();  /* barrier B */                                         \
        if (wrp < 21) {                                                           \
            const float4 a0 = *(const float4*)&sm[OFF_LA + 4 * rg];               \
            const float4 a1 = *(const float4*)&sm[OFF_LA + 32 + 4 * rg];          \
            const float4 a2 = *(const float4*)&sm[OFF_LA + 64 + 4 * rg];          \
            const float4 c0 = *(const float4*)&sm[OFF_LB + 4 * rg];               \
            const float4 c1 = *(const float4*)&sm[OFF_LB + 32 + 4 * rg];          \
            const float4 c2 = *(const float4*)&sm[OFF_LB + 64 + 4 * rg];          \
            float pA0 = a0.x + tlr[0], pA1 = a0.y + tlr[1];                       \
            float pB0 = c0.x + tlr[0], pB1 = c0.y + tlr[1];                       \
            pA0 = fmaxf(pA0, a0.z + tlr[2]);  pA1 = fmaxf(pA1, a0.w + tlr[3]);    \
            pB0 = fmaxf(pB0, c0.z + tlr[2]);  pB1 = fmaxf(pB1, c0.w + tlr[3]);    \
            pA0 = fmaxf(pA0, a1.x + tlr[4]);  pA1 = fmaxf(pA1, a1.y + tlr[5]);    \
            pB0 = fmaxf(pB0, c1.x + tlr[4]);  pB1 = fmaxf(pB1, c1.y + tlr[5]);    \
            pA0 = fmaxf(pA0, a1.z + tlr[6]);  pA1 = fmaxf(pA1, a1.w + tlr[7]);    \
            pB0 = fmaxf(pB0, c1.z + tlr[6]);  pB1 = fmaxf(pB1, c1.w + tlr[7]);    \
            pA0 = fmaxf(pA0, a2.x + tlr[8]);  pA1 = fmaxf(pA1, a2.y + tlr[9]);    \
            pB0 = fmaxf(pB0, c2.x + tlr[8]);  pB1 = fmaxf(pB1, c2.y + tlr[9]);    \
            pA0 = fmaxf(pA0, a2.z + tlr[10]); pA1 = fmaxf(pA1, a2.w + tlr[11]);   \
            pB0 = fmaxf(pB0, c2.z + tlr[10]); pB1 = fmaxf(pB1, c2.w + tlr[11]);   \
            float bestA = fmaxf(pA0, pA1);                                        \
            float bestB = fmaxf(pB0, pB1);                                        \
            bestA = fmaxf(bestA, __shfl_xor_sync(0xffffffffu, bestA, 1));         \
            bestB = fmaxf(bestB, __shfl_xor_sync(0xffffffffu, bestB, 1));         \
            bestA = fmaxf(bestA, __shfl_xor_sync(0xffffffffu, bestA, 2));         \
            bestB = fmaxf(bestB, __shfl_xor_sync(0xffffffffu, bestB, 2));         \
            bestA = fmaxf(bestA, __shfl_xor_sync(0xffffffffu, bestA, 4));         \
            bestB = fmaxf(bestB, __shfl_xor_sync(0xffffffffu, bestB, 4));         \
            if (rg == 0 && rj < NI) {                                             \
                sm[(NEXT) + baseRJ] = bestA + sm[OFF_BLP + (U) + 2];  /* vf(U+2) */ \
                sm[OFF_VF + rj]     = bestB + sm[OFF_BLP + (U) + 3];  /* vf(U+3) */ \
            }                                                                     \
        }                                                                         \
    } while (0)

    // 2999 blocks: delta(0) -> delta(5998); buffers alternate A->B->A...
    for (int u = 0; u < 5996; u += 4) {
        BLOCK(u,     OFF_A, OFF_B, lidxA);
        BLOCK(u + 2, OFF_B, OFF_A, lidxB);
    }
    BLOCK(5996, OFF_A, OFF_B, lidxA);    // delta(5998) in B; scratch = vf(5999)

    // ---- tail single step t=5999: B -> A (A becomes fully-valid delta(5999)) ----
    {
        __syncthreads();
        const float nbt = sm[OFF_NB + 5999];
        float x0 = sm[lidxT[0]], x1 = sm[lidxT[1]], x2 = sm[lidxT[2]], x3 = sm[lidxT[3]];
        float x4 = sm[lidxT[4]], x5 = sm[lidxT[5]], x6 = sm[lidxT[6]], x7 = sm[lidxT[7]];
        sm[OFF_A + tid             ] = fmaf(nbt, mT[0], x0);
        sm[OFF_A + tid + 1*NTHREADS] = fmaf(nbt, mT[1], x1);
        sm[OFF_A + tid + 2*NTHREADS] = fmaf(nbt, mT[2], x2);
        sm[OFF_A + tid + 3*NTHREADS] = fmaf(nbt, mT[3], x3);
        sm[OFF_A + tid + 4*NTHREADS] = fmaf(nbt, mT[4], x4);
        sm[OFF_A + tid + 5*NTHREADS] = fmaf(nbt, mT[5], x5);
        sm[OFF_A + tid + 6*NTHREADS] = fmaf(nbt, mT[6], x6);
        sm[OFF_A + tid + 7*NTHREADS] = fmaf(nbt, mT[7], x7);
    }
    __syncthreads();

    // ---- final argmax over delta(5999) in A, first-index tiebreak ----
    {
        float bv = NEGINF; int bs = NSTATE - 1;
        #pragma unroll
        for (int k = 0; k < NSLOTS; ++k) {
            if ((validM >> k) & 1u) {
                int s = tid + k * NTHREADS;
                float val = sm[OFF_A + s];
                if (val > bv) { bv = val; bs = s; }
            }
        }
        sm[OFF_RV + tid] = bv;
        ((int*)sm)[OFF_RI + tid] = bs;
    }
    __syncthreads();
    if (tid < NTHREADS - 512) {   // fold 512..767 into 0..255
        float v2 = sm[OFF_RV + tid + 512]; int s2 = ((int*)sm)[OFF_RI + tid + 512];
        if (v2 > sm[OFF_RV + tid] ||
            (v2 == sm[OFF_RV + tid] && s2 < ((int*)sm)[OFF_RI + tid])) {
            sm[OFF_RV + tid] = v2; ((int*)sm)[OFF_RI + tid] = s2;
        }
    }
    __syncthreads();
    for (int st = 256; st > 0; st >>= 1) {
        if (tid < st) {
            float v2 = sm[OFF_RV + tid + st]; int s2 = ((int*)sm)[OFF_RI + tid + st];
            if (v2 > sm[OFF_RV + tid] ||
                (v2 == sm[OFF_RV + tid] && s2 < ((int*)sm)[OFF_RI + tid])) {
                sm[OFF_RV + tid] = v2; ((int*)sm)[OFF_RI + tid] = s2;
            }
        }
        __syncthreads();
    }

    // ---- backtrack (thread 0): jump beat-to-beat, hard-bounded ----
    if (tid == 0) {
        const double p0  = (double)0.05f;
        const double thr = log(p0 / (1.0 - p0));   // logit-space threshold

        int s = ((int*)sm)[OFF_RI + 0];
        if (s < 0) s = 0;
        if (s >= NSTATE) s = NSTATE - 1;
        int j = 0;
        while (j < NI - 1 && base_of(j + 1) <= s) ++j;
        int p = s - base_of(j);
        int t = TT - 1;
        for (int iter = 0; iter < TT; ++iter) {
            if (p > t) break;            // path started mid-block: no beat
            int tb = t - p;              // beat time (position 0)
            double x = (double)lg[tb];
            outrow[tb] = (x >= thr) ? 1.0f : 0.0f;
            if (tb == 0) break;
            const float* row = &g_plbuf[b][tb][0];
            float mx = NEGINF; int bi = 0;
            for (int i = 0; i < NI; ++i) {
                float c = row[i] + sm[OFF_TL + i * NI + j];
                if (c > mx) { mx = c; bi = i; }
            }
            j = bi;
            t = tb - 1;
            p = (MINTAU + j) - 1;
        }
    }
}

extern "C" void kernel_launch(void* const* d_in, const int* in_sizes, int n_in,
                              void* d_out, int out_size)
{
    const float* logit = (const float*)d_in[0];
    float* out = (float*)d_out;

    size_t smem = (size_t)SM_FLOATS * sizeof(float);   // 131,296 B
    cudaFuncSetAttribute(dbn_viterbi_kernel,
                         cudaFuncAttributeMaxDynamicSharedMemorySize, (int)smem);
    dbn_viterbi_kernel<<<BB, NTHREADS, smem>>>(logit, out);
}